// round 4
// baseline (speedup 1.0000x reference)
#include <cuda_runtime.h>
#include <math.h>

#define BB 8
#define CC 128
#define HH 96
#define WWD 96
#define EE 8
#define NG 4
#define PIX 9216   // 96*96

// ---------------- device globals (no allocations allowed) ----------------
__device__ float g_xgap[BB][CC];
__device__ float g_wt[NG][BB][EE];     // combine weight per (gate, batch, expert)
__device__ int   g_mask[EE][BB];       // 1 if (e,b) pair is selected by any gate
__device__ float g_beff[NG][BB][CC];   // effective bias sum_e w*bp
__device__ float g_u[(size_t)EE * BB * CC * PIX];  // squashed conv outputs (~302 MB)

// ---------------- K0: global average pool x -> g_xgap ----------------
__global__ void k_gap(const float* __restrict__ x) {
    int bc = blockIdx.x;                 // b*128 + c
    const float* p = x + (size_t)bc * PIX;
    float s = 0.f;
    for (int i = threadIdx.x; i < PIX; i += 256) s += p[i];
    __shared__ float red[8];
    #pragma unroll
    for (int o = 16; o; o >>= 1) s += __shfl_down_sync(0xffffffffu, s, o);
    if ((threadIdx.x & 31) == 0) red[threadIdx.x >> 5] = s;
    __syncthreads();
    if (threadIdx.x < 8) {
        s = red[threadIdx.x];
        #pragma unroll
        for (int o = 4; o; o >>= 1) s += __shfl_down_sync(0xffu, s, o);
        if (threadIdx.x == 0) g_xgap[bc >> 7][bc & 127] = s * (1.0f / PIX);
    }
}

// ---------------- K1: gating, top-2, combine weights, loss ----------------
__global__ void k_gate(const float* __restrict__ G, const float* __restrict__ bp,
                       float* __restrict__ dout) {
    __shared__ float probs[BB][EE];
    __shared__ float losses[NG];
    int t = threadIdx.x;
    if (t < EE * BB) g_mask[t / BB][t % BB] = 0;
    __syncthreads();

    for (int g = 0; g < NG; g++) {
        if (t < BB * EE) {
            int b = t >> 3, e = t & 7;
            float s = 0.f;
            for (int c = 0; c < CC; c++) s += g_xgap[b][c] * G[(g * CC + c) * EE + e];
            probs[b][e] = s;   // logits for now
        }
        __syncthreads();
        if (t < BB) {
            int b = t;
            float mx = probs[b][0];
            #pragma unroll
            for (int e = 1; e < EE; e++) mx = fmaxf(mx, probs[b][e]);
            float pr[EE]; float sum = 0.f;
            #pragma unroll
            for (int e = 0; e < EE; e++) { pr[e] = expf(probs[b][e] - mx); sum += pr[e]; }
            float inv = 1.f / sum;
            #pragma unroll
            for (int e = 0; e < EE; e++) { pr[e] *= inv; probs[b][e] = pr[e]; }
            // top-2 (stable: strict > keeps lowest index on tie, matching jax)
            int i0 = 0;
            #pragma unroll
            for (int e = 1; e < EE; e++) if (pr[e] > pr[i0]) i0 = e;
            int i1 = (i0 == 0) ? 1 : 0;
            #pragma unroll
            for (int e = 0; e < EE; e++) if (e != i0 && pr[e] > pr[i1]) i1 = e;
            // tw = softmax over the top-2 prob VALUES (reference softmaxes tv)
            float e1 = expf(pr[i1] - pr[i0]);
            float tw0 = 1.f / (1.f + e1), tw1 = e1 / (1.f + e1);
            #pragma unroll
            for (int e = 0; e < EE; e++) g_wt[g][b][e] = 0.f;
            g_wt[g][b][i0] = tw0; g_wt[g][b][i1] = tw1;
            g_mask[i0][b] = 1; g_mask[i1][b] = 1;
        }
        __syncthreads();
        if (t == 0) {
            float v[EE]; float mean = 0.f;
            #pragma unroll
            for (int e = 0; e < EE; e++) {
                float s = 0.f;
                for (int b = 0; b < BB; b++) s += probs[b][e];
                v[e] = s; mean += s;
            }
            mean *= (1.0f / EE);
            float var = 0.f;
            #pragma unroll
            for (int e = 0; e < EE; e++) { float d = v[e] - mean; var += d * d; }
            var *= (1.0f / (EE - 1));
            losses[g] = var / (mean * mean + 1e-10f);
        }
        __syncthreads();
    }
    // effective bias per (gate, batch, channel)
    if (t < CC) {
        for (int g = 0; g < NG; g++)
            for (int b = 0; b < BB; b++) {
                float s = 0.f;
                #pragma unroll
                for (int e = 0; e < EE; e++) s += g_wt[g][b][e] * bp[e * CC + t];
                g_beff[g][b][t] = s;
            }
    }
    if (t == 0)
        dout[(size_t)NG * BB * CC * PIX] =
            0.25f * (losses[0] + losses[1] + losses[2] + losses[3]);
}

// ---------------- K2: 3x3 conv + bias + relu + squash for selected pairs ----------------
// Block: 256 threads; tile = 8x8 pixels x all 128 output channels.
// Thread t: row r = t&7 (8 pixels wide), c_out group cog = t>>3 (4 channels).
__global__ void __launch_bounds__(256, 4) k_conv(const float* __restrict__ x,
                                                 const float* __restrict__ Wc,
                                                 const float* __restrict__ bc) {
    int e = blockIdx.z, b = blockIdx.y;
    if (!g_mask[e][b]) return;
    int th = blockIdx.x / 12, tw = blockIdx.x % 12;
    int h0 = th * 8, w0 = tw * 8;

    __shared__ float xs[8][10][13];     // 8 c_in x 10x10 halo, row pad 13
    __shared__ float ws2[128][73];      // [c_out][ci*9+tap], pad 73
    __shared__ float sn[64];            // per-pixel sum of squares

    int t = threadIdx.x;
    int r = t & 7, cog = t >> 3;

    float acc[4][8];
    #pragma unroll
    for (int i = 0; i < 4; i++)
        #pragma unroll
        for (int j = 0; j < 8; j++) acc[i][j] = 0.f;

    const float* xb = x + (size_t)b * CC * PIX;
    const float* wb = Wc + (size_t)e * CC * CC * 9;

    for (int cc = 0; cc < CC; cc += 8) {
        __syncthreads();
        // load x halo: 8 c_in x 10 x 10
        for (int i = t; i < 800; i += 256) {
            int ci = i / 100, rr = (i % 100) / 10, cl = i % 10;
            int hh = h0 + rr - 1, ww = w0 + cl - 1;
            float v = 0.f;
            if ((unsigned)hh < 96u && (unsigned)ww < 96u)
                v = xb[(size_t)(cc + ci) * PIX + hh * 96 + ww];
            xs[ci][rr][cl] = v;
        }
        // load weights: coalesced 72-float runs; conflict-free store (stride 1)
        for (int i = t; i < 9216; i += 256) {
            int co = i / 72, ct = i % 72;
            ws2[co][ct] = wb[(size_t)co * 1152 + cc * 9 + ct];
        }
        __syncthreads();
        #pragma unroll
        for (int ci = 0; ci < 8; ci++) {
            #pragma unroll
            for (int dh = 0; dh < 3; dh++) {
                float xr[10];
                #pragma unroll
                for (int k = 0; k < 10; k++) xr[k] = xs[ci][r + dh][k];
                #pragma unroll
                for (int dw = 0; dw < 3; dw++) {
                    int tap = ci * 9 + dh * 3 + dw;
                    float w0v = ws2[cog * 4 + 0][tap];
                    float w1v = ws2[cog * 4 + 1][tap];
                    float w2v = ws2[cog * 4 + 2][tap];
                    float w3v = ws2[cog * 4 + 3][tap];
                    #pragma unroll
                    for (int j = 0; j < 8; j++) {
                        float xv = xr[dw + j];
                        acc[0][j] += w0v * xv;
                        acc[1][j] += w1v * xv;
                        acc[2][j] += w2v * xv;
                        acc[3][j] += w3v * xv;
                    }
                }
            }
        }
    }

    // bias + relu + per-pixel channel sum-of-squares
    __syncthreads();
    if (t < 64) sn[t] = 0.f;
    __syncthreads();
    float bv[4];
    #pragma unroll
    for (int i = 0; i < 4; i++) bv[i] = bc[e * CC + cog * 4 + i];
    #pragma unroll
    for (int j = 0; j < 8; j++) {
        float p = 0.f;
        #pragma unroll
        for (int i = 0; i < 4; i++) {
            float v = fmaxf(acc[i][j] + bv[i], 0.f);
            acc[i][j] = v; p += v * v;
        }
        atomicAdd(&sn[r * 8 + j], p);
    }
    __syncthreads();

    float sc[8];
    #pragma unroll
    for (int j = 0; j < 8; j++) {
        float s = sn[r * 8 + j];
        sc[j] = s / (1.f + s) * rsqrtf(s + 1e-8f);
    }
    float* ub = g_u + (size_t)(e * BB + b) * CC * PIX;
    #pragma unroll
    for (int i = 0; i < 4; i++) {
        int c = cog * 4 + i;
        float* dst = ub + (size_t)c * PIX + (h0 + r) * 96 + w0;
        float4 v0 = make_float4(acc[i][0] * sc[0], acc[i][1] * sc[1],
                                acc[i][2] * sc[2], acc[i][3] * sc[3]);
        float4 v1 = make_float4(acc[i][4] * sc[4], acc[i][5] * sc[5],
                                acc[i][6] * sc[6], acc[i][7] * sc[7]);
        *(float4*)dst = v0;
        *(float4*)(dst + 4) = v1;
    }
}

// ---------------- K3: 1x1 conv + gate combine + bias, writes all 4 outputs ----------------
// Block: 256 threads, tile = 32 pixels x 128 out channels for one batch b.
// Thread: pg = t&15 (pixel pair), og = t>>4 (8 out channels).
__global__ void __launch_bounds__(256, 2) k_pw(const float* __restrict__ Wp,
                                               float* __restrict__ out) {
    int b = blockIdx.y;
    int pix0 = blockIdx.x * 32;
    __shared__ float su[64][32];
    __shared__ float swp[64][132];   // pad 132 keeps float4 rows aligned
    int t = threadIdx.x;
    int pg = t & 15, og = t >> 4;

    float accg[4][8][2];
    #pragma unroll
    for (int g = 0; g < 4; g++)
        #pragma unroll
        for (int i = 0; i < 8; i++) { accg[g][i][0] = 0.f; accg[g][i][1] = 0.f; }

    for (int e = 0; e < EE; e++) {
        if (!g_mask[e][b]) continue;   // uniform across block
        float y[8][2];
        #pragma unroll
        for (int i = 0; i < 8; i++) { y[i][0] = 0.f; y[i][1] = 0.f; }
        const float* ub = g_u + (size_t)(e * BB + b) * CC * PIX + pix0;
        const float* wpb = Wp + (size_t)e * CC * CC;
        for (int ch = 0; ch < 2; ch++) {
            int c0 = ch * 64;
            __syncthreads();
            for (int i = t; i < 2048; i += 256) {
                int ci = i >> 5, p = i & 31;
                su[ci][p] = ub[(size_t)(c0 + ci) * PIX + p];
            }
            for (int i = t; i < 8192; i += 256) {
                int o = i >> 6, ci = i & 63;
                swp[ci][o] = wpb[o * CC + c0 + ci];
            }
            __syncthreads();
            #pragma unroll 16
            for (int ci = 0; ci < 64; ci++) {
                float2 u2 = *(float2*)&su[ci][pg * 2];
                float4 wA = *(float4*)&swp[ci][og * 8];
                float4 wB = *(float4*)&swp[ci][og * 8 + 4];
                y[0][0] += wA.x * u2.x; y[0][1] += wA.x * u2.y;
                y[1][0] += wA.y * u2.x; y[1][1] += wA.y * u2.y;
                y[2][0] += wA.z * u2.x; y[2][1] += wA.z * u2.y;
                y[3][0] += wA.w * u2.x; y[3][1] += wA.w * u2.y;
                y[4][0] += wB.x * u2.x; y[4][1] += wB.x * u2.y;
                y[5][0] += wB.y * u2.x; y[5][1] += wB.y * u2.y;
                y[6][0] += wB.z * u2.x; y[6][1] += wB.z * u2.y;
                y[7][0] += wB.w * u2.x; y[7][1] += wB.w * u2.y;
            }
        }
        #pragma unroll
        for (int g = 0; g < 4; g++) {
            float w = g_wt[g][b][e];
            #pragma unroll
            for (int i = 0; i < 8; i++) {
                accg[g][i][0] += w * y[i][0];
                accg[g][i][1] += w * y[i][1];
            }
        }
    }
    #pragma unroll
    for (int g = 0; g < 4; g++) {
        #pragma unroll
        for (int i = 0; i < 8; i++) {
            int o = og * 8 + i;
            float be = g_beff[g][b][o];
            float2 v = make_float2(accg[g][i][0] + be, accg[g][i][1] + be);
            *(float2*)&out[(size_t)g * BB * CC * PIX + ((size_t)b * CC + o) * PIX +
                           pix0 + pg * 2] = v;
        }
    }
}

// ---------------- launch ----------------
extern "C" void kernel_launch(void* const* d_in, const int* in_sizes, int n_in,
                              void* d_out, int out_size) {
    const float* x  = (const float*)d_in[0];
    const float* G  = (const float*)d_in[1];
    const float* Wc = (const float*)d_in[2];
    const float* bc = (const float*)d_in[3];
    const float* Wp = (const float*)d_in[4];
    const float* bp = (const float*)d_in[5];
    float* out = (float*)d_out;

    k_gap<<<BB * CC, 256>>>(x);
    k_gate<<<1, 128>>>(G, bp, out);
    k_conv<<<dim3(144, BB, EE), 256>>>(x, Wc, bc);
    k_pw<<<dim3(PIX / 32, BB), 256>>>(Wp, out);
}

// round 6
// speedup vs baseline: 3.3925x; 3.3925x over previous
#include <cuda_runtime.h>
#include <math.h>
#include <stdint.h>

#define BB 8
#define CC 128
#define EE 8
#define NG 4
#define PIX 9216
#define XROWS 10240     // g_xt rows: 128 lead pad + pp(max 9506) + halo slack
#define NTT 75          // M-tiles of 128 padded pixels (covers pp<=9599>=9506)
#define UROWS 9600      // u plane rows

// ---------------- device globals ----------------
__device__ float g_xgap[BB][CC];
__device__ float g_wt[NG][BB][EE];
__device__ int   g_sel[NG][BB][2];
__device__ int   g_mask[EE][BB];
__device__ float g_beff[NG][BB][CC];
__device__ uint32_t g_xt[(size_t)BB*4*XROWS*32];      // tf32 x, [b][cchunk][row][32ci]
__device__ uint32_t g_wtb[(size_t)EE*9*4*32*CC];      // tf32 conv W, [e,tap,chunk][ci32][co128]
__device__ uint32_t g_bp[(size_t)NG*BB*2*CC*CC];      // tf32 gate-scaled pw W, [g,b,slot][ci128][co128]
__device__ uint32_t g_ub[(size_t)EE*BB*UROWS*CC];     // tf32 squashed u, [pair][row][128ci]

// ---------------- helpers ----------------
__device__ __forceinline__ uint32_t f2tf32(float f) {
    uint32_t r; asm("cvt.rna.tf32.f32 %0, %1;" : "=r"(r) : "f"(f)); return r;
}
__device__ __forceinline__ void mma8(float* c, const uint32_t* a, uint32_t b0, uint32_t b1) {
    asm volatile(
        "mma.sync.aligned.m16n8k8.row.col.f32.tf32.tf32.f32 "
        "{%0,%1,%2,%3},{%4,%5,%6,%7},{%8,%9},{%0,%1,%2,%3};"
        : "+f"(c[0]), "+f"(c[1]), "+f"(c[2]), "+f"(c[3])
        : "r"(a[0]), "r"(a[1]), "r"(a[2]), "r"(a[3]), "r"(b0), "r"(b1));
}

// ---------------- K0: global average pool ----------------
__global__ void k_gap(const float* __restrict__ x) {
    int bc = blockIdx.x;
    const float* p = x + (size_t)bc * PIX;
    float s = 0.f;
    for (int i = threadIdx.x; i < PIX; i += 256) s += p[i];
    __shared__ float red[8];
    #pragma unroll
    for (int o = 16; o; o >>= 1) s += __shfl_down_sync(0xffffffffu, s, o);
    if ((threadIdx.x & 31) == 0) red[threadIdx.x >> 5] = s;
    __syncthreads();
    if (threadIdx.x < 8) {
        s = red[threadIdx.x];
        #pragma unroll
        for (int o = 4; o; o >>= 1) s += __shfl_down_sync(0xffu, s, o);
        if (threadIdx.x == 0) g_xgap[bc >> 7][bc & 127] = s * (1.0f / PIX);
    }
}

// ---------------- K1: gating, top-2, combine weights, loss ----------------
__global__ void k_gate(const float* __restrict__ G, const float* __restrict__ bp,
                       float* __restrict__ dout) {
    __shared__ float probs[BB][EE];
    __shared__ float losses[NG];
    int t = threadIdx.x;
    if (t < EE * BB) g_mask[t / BB][t % BB] = 0;
    __syncthreads();
    for (int g = 0; g < NG; g++) {
        if (t < BB * EE) {
            int b = t >> 3, e = t & 7;
            float s = 0.f;
            for (int c = 0; c < CC; c++) s += g_xgap[b][c] * G[(g * CC + c) * EE + e];
            probs[b][e] = s;
        }
        __syncthreads();
        if (t < BB) {
            int b = t;
            float mx = probs[b][0];
            #pragma unroll
            for (int e = 1; e < EE; e++) mx = fmaxf(mx, probs[b][e]);
            float pr[EE]; float sum = 0.f;
            #pragma unroll
            for (int e = 0; e < EE; e++) { pr[e] = expf(probs[b][e] - mx); sum += pr[e]; }
            float inv = 1.f / sum;
            #pragma unroll
            for (int e = 0; e < EE; e++) { pr[e] *= inv; probs[b][e] = pr[e]; }
            int i0 = 0;
            #pragma unroll
            for (int e = 1; e < EE; e++) if (pr[e] > pr[i0]) i0 = e;
            int i1 = (i0 == 0) ? 1 : 0;
            #pragma unroll
            for (int e = 0; e < EE; e++) if (e != i0 && pr[e] > pr[i1]) i1 = e;
            float e1 = expf(pr[i1] - pr[i0]);
            float tw0 = 1.f / (1.f + e1), tw1 = e1 / (1.f + e1);
            #pragma unroll
            for (int e = 0; e < EE; e++) g_wt[g][b][e] = 0.f;
            g_wt[g][b][i0] = tw0; g_wt[g][b][i1] = tw1;
            g_sel[g][b][0] = i0; g_sel[g][b][1] = i1;
            g_mask[i0][b] = 1; g_mask[i1][b] = 1;
        }
        __syncthreads();
        if (t == 0) {
            float v[EE]; float mean = 0.f;
            #pragma unroll
            for (int e = 0; e < EE; e++) {
                float s = 0.f;
                for (int b = 0; b < BB; b++) s += probs[b][e];
                v[e] = s; mean += s;
            }
            mean *= (1.0f / EE);
            float var = 0.f;
            #pragma unroll
            for (int e = 0; e < EE; e++) { float d = v[e] - mean; var += d * d; }
            var *= (1.0f / (EE - 1));
            losses[g] = var / (mean * mean + 1e-10f);
        }
        __syncthreads();
    }
    if (t < CC) {
        for (int g = 0; g < NG; g++)
            for (int b = 0; b < BB; b++) {
                float s = 0.f;
                #pragma unroll
                for (int e = 0; e < EE; e++) s += g_wt[g][b][e] * bp[e * CC + t];
                g_beff[g][b][t] = s;
            }
    }
    if (t == 0)
        dout[(size_t)NG * BB * CC * PIX] =
            0.25f * (losses[0] + losses[1] + losses[2] + losses[3]);
}

// ---------------- pack x -> padded pixel-major tf32 planes ----------------
__global__ void k_packx(const float* __restrict__ x) {
    int b = blockIdx.y, p0 = blockIdx.x * 64;
    __shared__ float sx[128][65];
    int t = threadIdx.x;
    for (int i = t; i < 8192; i += 256) {
        int ci = i >> 6, p = i & 63;
        sx[ci][p] = x[((size_t)b * CC + ci) * PIX + p0 + p];
    }
    __syncthreads();
    for (int i = t; i < 2048; i += 256) {
        int p = i >> 5, c = (i >> 3) & 3, q = i & 7;
        int dp = p0 + p, h = dp / 96, w = dp % 96;
        int pp = (h + 1) * 98 + (w + 1) + 128;   // 128-row lead pad
        uint4 v;
        v.x = f2tf32(sx[c * 32 + q * 4 + 0][p]);
        v.y = f2tf32(sx[c * 32 + q * 4 + 1][p]);
        v.z = f2tf32(sx[c * 32 + q * 4 + 2][p]);
        v.w = f2tf32(sx[c * 32 + q * 4 + 3][p]);
        *(uint4*)&g_xt[(((size_t)b * 4 + c) * XROWS + pp) * 32 + q * 4] = v;
    }
}

// ---------------- pack conv weights: [e,tap,chunk][ci32][co128] ----------------
__global__ void k_packw(const float* __restrict__ Wc) {
    int idx = blockIdx.x * 256 + threadIdx.x;      // 294912 uint4
    int c4 = idx & 31, ci = (idx >> 5) & 31, c = (idx >> 10) & 3;
    int et = idx >> 12, tap = et % 9, e = et / 9;
    int co = c4 * 4;
    const float* s = Wc + (((size_t)(e * CC + co) * CC + c * 32 + ci) * 9 + tap);
    uint4 v;
    v.x = f2tf32(s[0]);
    v.y = f2tf32(s[1152]);
    v.z = f2tf32(s[2304]);
    v.w = f2tf32(s[3456]);
    ((uint4*)g_wtb)[idx] = v;
}

// ---------------- pack gate-scaled pw weights: [g,b,slot][ci128][co128] ----------------
__global__ void k_packbp(const float* __restrict__ Wp) {
    int idx = blockIdx.x * 256 + threadIdx.x;      // 262144 uint4
    int c4 = idx & 31, ci = (idx >> 5) & 127, slot = (idx >> 12) & 1;
    int b = (idx >> 13) & 7, g = idx >> 16;
    int e = g_sel[g][b][slot];
    float wv = g_wt[g][b][e];
    int co = c4 * 4;
    const float* s = Wp + (size_t)e * CC * CC + (size_t)co * CC + ci;
    uint4 v;
    v.x = f2tf32(s[0]   * wv);
    v.y = f2tf32(s[128] * wv);
    v.z = f2tf32(s[256] * wv);
    v.w = f2tf32(s[384] * wv);
    ((uint4*)g_bp)[idx] = v;
}

// ---------------- conv: mma.sync tf32, 9 shifted GEMMs, fused bias/relu/squash ----------
// block 256 = 8 warps; block tile 128 pix x 128 cout; warp tile 32x64 (wm=wid&3, wn=wid>>2)
#define XS_W 36
#define WS_W 136
#define CV_XS 0
#define CV_WS 11736              // 326*36
#define CV_BIAS (11736 + 8704)   // + 2*32*136
#define CV_SS   (CV_BIAS + 128)
#define CV_SMEMB ((CV_SS + 128) * 4)

__global__ void __launch_bounds__(256) k_conv_mma(const float* __restrict__ bc) {
    int e = blockIdx.z, b = blockIdx.y;
    if (!g_mask[e][b]) return;
    extern __shared__ uint32_t S[];
    uint32_t* xs = S + CV_XS;
    uint32_t* ws = S + CV_WS;
    float* bias = (float*)(S + CV_BIAS);
    float* ssm  = (float*)(S + CV_SS);
    int t = threadIdx.x, lane = t & 31, wid = t >> 5;
    int wm = wid & 3, wn = wid >> 2;
    int gp = lane >> 2, tg = lane & 3;
    int q0 = blockIdx.x * 128;
    if (t < 128) { bias[t] = bc[e * CC + t]; ssm[t] = 0.f; }
    float acc[2][8][4];
    #pragma unroll
    for (int mt = 0; mt < 2; mt++)
        #pragma unroll
        for (int nt = 0; nt < 8; nt++)
            #pragma unroll
            for (int k = 0; k < 4; k++) acc[mt][nt][k] = 0.f;
    const int drow[9] = {0, 1, 2, 98, 99, 100, 196, 197, 198};

    for (int c = 0; c < 4; c++) {
        __syncthreads();
        const uint4* xsrc = (const uint4*)(g_xt + (((size_t)b * 4 + c) * XROWS + q0 + 29) * 32);
        for (int i = t; i < 2608; i += 256) {
            int r = i >> 3, q = i & 7;
            uint4 v = xsrc[i];
            *(uint4*)&xs[r * XS_W + q * 4] = v;
        }
        {   // ws tap0 -> buf0
            const uint4* wsrc = (const uint4*)(g_wtb + ((size_t)((e * 9 + 0) * 4 + c)) * 4096);
            for (int i = t; i < 1024; i += 256) {
                int ci = i >> 5, c4 = i & 31;
                *(uint4*)&ws[ci * WS_W + c4 * 4] = wsrc[i];
            }
        }
        __syncthreads();
        for (int tap = 0; tap < 9; tap++) {
            int cur = tap & 1, nxt = cur ^ 1;
            uint4 pf[4];
            bool havepf = (tap < 8);
            if (havepf) {
                const uint4* wsrc = (const uint4*)(g_wtb + ((size_t)((e * 9 + tap + 1) * 4 + c)) * 4096);
                #pragma unroll
                for (int j = 0; j < 4; j++) pf[j] = wsrc[t + j * 256];
            }
            uint32_t* wc_ = ws + cur * 4352;
            int rb = wm * 32 + gp + drow[tap];
            #pragma unroll
            for (int k8 = 0; k8 < 4; k8++) {
                int k0 = k8 * 8 + tg;
                uint32_t a[2][4];
                #pragma unroll
                for (int mt = 0; mt < 2; mt++) {
                    const uint32_t* xp = xs + (rb + mt * 16) * XS_W;
                    a[mt][0] = xp[k0];
                    a[mt][1] = xp[8 * XS_W + k0];
                    a[mt][2] = xp[k0 + 4];
                    a[mt][3] = xp[8 * XS_W + k0 + 4];
                }
                #pragma unroll
                for (int nt = 0; nt < 8; nt++) {
                    int n = wn * 64 + nt * 8 + gp;
                    uint32_t b0 = wc_[k0 * WS_W + n];
                    uint32_t b1 = wc_[(k0 + 4) * WS_W + n];
                    mma8(acc[0][nt], a[0], b0, b1);
                    mma8(acc[1][nt], a[1], b0, b1);
                }
            }
            if (havepf) {
                uint32_t* wd = ws + nxt * 4352;
                #pragma unroll
                for (int j = 0; j < 4; j++) {
                    int i = t + j * 256;
                    int ci = i >> 5, c4 = i & 31;
                    *(uint4*)&wd[ci * WS_W + c4 * 4] = pf[j];
                }
            }
            __syncthreads();
        }
    }
    // epilogue: bias + relu + per-pixel squash + tf32 store
    float ssq[2][2] = {{0.f, 0.f}, {0.f, 0.f}};
    #pragma unroll
    for (int mt = 0; mt < 2; mt++)
        #pragma unroll
        for (int nt = 0; nt < 8; nt++)
            #pragma unroll
            for (int k = 0; k < 4; k++) {
                int col = wn * 64 + nt * 8 + 2 * tg + (k & 1);
                float v = fmaxf(acc[mt][nt][k] + bias[col], 0.f);
                acc[mt][nt][k] = v;
                ssq[mt][k >> 1] += v * v;
            }
    #pragma unroll
    for (int mt = 0; mt < 2; mt++)
        #pragma unroll
        for (int h = 0; h < 2; h++) {
            float s = ssq[mt][h];
            s += __shfl_xor_sync(0xffffffffu, s, 1);
            s += __shfl_xor_sync(0xffffffffu, s, 2);
            if (tg == 0) atomicAdd(&ssm[wm * 32 + mt * 16 + gp + 8 * h], s);
        }
    __syncthreads();
    uint32_t* up = g_ub + (size_t)(e * BB + b) * UROWS * CC;
    #pragma unroll
    for (int mt = 0; mt < 2; mt++)
        #pragma unroll
        for (int h = 0; h < 2; h++) {
            int r = wm * 32 + mt * 16 + gp + 8 * h;
            float s = ssm[r];
            float sc = s / (1.f + s) * rsqrtf(s + 1e-8f);
            #pragma unroll
            for (int nt = 0; nt < 8; nt++) {
                uint2 v;
                v.x = f2tf32(acc[mt][nt][h * 2] * sc);
                v.y = f2tf32(acc[mt][nt][h * 2 + 1] * sc);
                *(uint2*)&up[(size_t)(q0 + r) * CC + wn * 64 + nt * 8 + 2 * tg] = v;
            }
        }
}

// ---------------- pw: per-(gate,b) K-stacked GEMM over its 2 experts ----------------
#define PW_US 0
#define PW_WS 4608               // 128*36
#define PW_BIAS (4608 + 4352)    // + 32*136
#define PW_SMEMB ((PW_BIAS + 128) * 4)

__global__ void __launch_bounds__(256) k_pw_mma(float* __restrict__ out) {
    int g = blockIdx.z, b = blockIdx.y, q0 = blockIdx.x * 128;
    extern __shared__ uint32_t S[];
    uint32_t* us = S + PW_US;
    uint32_t* ws = S + PW_WS;
    float* bias = (float*)(S + PW_BIAS);
    int t = threadIdx.x, lane = t & 31, wid = t >> 5;
    int wm = wid & 3, wn = wid >> 2;
    int gp = lane >> 2, tg = lane & 3;
    if (t < 128) bias[t] = g_beff[g][b][t];
    float acc[2][8][4];
    #pragma unroll
    for (int mt = 0; mt < 2; mt++)
        #pragma unroll
        for (int nt = 0; nt < 8; nt++)
            #pragma unroll
            for (int k = 0; k < 4; k++) acc[mt][nt][k] = 0.f;

    for (int kc = 0; kc < 8; kc++) {
        int slot = kc >> 2, c = kc & 3;
        int e = g_sel[g][b][slot];
        __syncthreads();
        const uint32_t* usrc = g_ub + ((size_t)(e * BB + b) * UROWS + q0) * CC + c * 32;
        for (int i = t; i < 1024; i += 256) {
            int r = i >> 3, q = i & 7;
            uint4 v = *(const uint4*)(usrc + (size_t)r * CC + q * 4);
            *(uint4*)&us[r * XS_W + q * 4] = v;
        }
        const uint4* wsrc = (const uint4*)(g_bp + ((size_t)((g * BB + b) * 2 + slot)) * CC * CC
                                           + (size_t)c * 32 * CC);
        for (int i = t; i < 1024; i += 256) {
            int ci = i >> 5, c4 = i & 31;
            *(uint4*)&ws[ci * WS_W + c4 * 4] = wsrc[i];
        }
        __syncthreads();
        int rb = wm * 32 + gp;
        #pragma unroll
        for (int k8 = 0; k8 < 4; k8++) {
            int k0 = k8 * 8 + tg;
            uint32_t a[2][4];
            #pragma unroll
            for (int mt = 0; mt < 2; mt++) {
                const uint32_t* xp = us + (rb + mt * 16) * XS_W;
                a[mt][0] = xp[k0];
                a[mt][1] = xp[8 * XS_W + k0];
                a[mt][2] = xp[k0 + 4];
                a[mt][3] = xp[8 * XS_W + k0 + 4];
            }
            #pragma unroll
            for (int nt = 0; nt < 8; nt++) {
                int n = wn * 64 + nt * 8 + gp;
                uint32_t b0 = ws[k0 * WS_W + n];
                uint32_t b1 = ws[(k0 + 4) * WS_W + n];
                mma8(acc[0][nt], a[0], b0, b1);
                mma8(acc[1][nt], a[1], b0, b1);
            }
        }
    }
    // epilogue: + bias, map padded pixel -> (h,w), write valid
    #pragma unroll
    for (int mt = 0; mt < 2; mt++)
        #pragma unroll
        for (int k = 0; k < 4; k++) {
            int r = wm * 32 + mt * 16 + gp + 8 * (k >> 1);
            int q = q0 + r;
            int h = q / 98 - 1, w = q % 98 - 1;
            if ((unsigned)h < 96u && (unsigned)w < 96u) {
                #pragma unroll
                for (int nt = 0; nt < 8; nt++) {
                    int col = wn * 64 + nt * 8 + 2 * tg + (k & 1);
                    out[(((size_t)g * BB + b) * CC + col) * PIX + h * 96 + w] =
                        acc[mt][nt][k] + bias[col];
                }
            }
        }
}

// ---------------- launch ----------------
extern "C" void kernel_launch(void* const* d_in, const int* in_sizes, int n_in,
                              void* d_out, int out_size) {
    const float* x  = (const float*)d_in[0];
    const float* G  = (const float*)d_in[1];
    const float* Wc = (const float*)d_in[2];
    const float* bc = (const float*)d_in[3];
    const float* Wp = (const float*)d_in[4];
    const float* bp = (const float*)d_in[5];
    float* out = (float*)d_out;

    cudaFuncSetAttribute(k_conv_mma, cudaFuncAttributeMaxDynamicSharedMemorySize, CV_SMEMB);

    k_gap<<<BB * CC, 256>>>(x);
    k_gate<<<1, 128>>>(G, bp, out);
    k_packx<<<dim3(144, BB), 256>>>(x);
    k_packw<<<1152, 256>>>(Wc);
    k_packbp<<<1024, 256>>>(Wp);
    k_conv_mma<<<dim3(NTT, BB, EE), 256, CV_SMEMB>>>(bc);
    k_pw_mma<<<dim3(NTT, BB, NG), 256, PW_SMEMB>>>(out);
}

// round 7
// speedup vs baseline: 4.0976x; 1.2078x over previous
#include <cuda_runtime.h>
#include <math.h>
#include <stdint.h>

#define BB 8
#define CC 128
#define EE 8
#define NG 4
#define PIX 9216
#define XROWS 10240     // g_xt rows: 128 lead pad + pp + halo slack
#define NTT 75          // pw M-tiles of 128 padded pixels
#define NT2 38          // conv M-tiles of 256 padded pixels
#define UROWS 9600      // u plane rows

// ---------------- device globals ----------------
__device__ float g_xgap[BB][CC];
__device__ float g_wt[NG][BB][EE];
__device__ int   g_sel[NG][BB][2];
__device__ int   g_mask[EE][BB];
__device__ float g_beff[NG][BB][CC];
__device__ uint32_t g_xt[(size_t)BB*4*XROWS*32];      // tf32 x, [b][cchunk][row][32ci]
__device__ uint32_t g_wtb[(size_t)EE*9*4*32*CC];      // tf32 conv W, [e,tap,chunk][ci32][co128]
__device__ uint32_t g_bp[(size_t)NG*BB*2*CC*CC];      // tf32 gate-scaled pw W
__device__ uint32_t g_ub[(size_t)EE*BB*UROWS*CC];     // tf32 squashed u, [pair][row][128ci]

// ---------------- helpers ----------------
__device__ __forceinline__ uint32_t f2tf32(float f) {
    uint32_t r; asm("cvt.rna.tf32.f32 %0, %1;" : "=r"(r) : "f"(f)); return r;
}
__device__ __forceinline__ uint32_t smem_u32(const void* p) {
    uint32_t a;
    asm("{ .reg .u64 t; cvta.to.shared.u64 t, %1; cvt.u32.u64 %0, t; }" : "=r"(a) : "l"(p));
    return a;
}
__device__ __forceinline__ void cpa16(uint32_t dst, const void* src) {
    asm volatile("cp.async.cg.shared.global [%0], [%1], 16;" :: "r"(dst), "l"(src) : "memory");
}
__device__ __forceinline__ void cpa_commit() {
    asm volatile("cp.async.commit_group;" ::: "memory");
}
__device__ __forceinline__ void cpa_wait1() {
    asm volatile("cp.async.wait_group 1;" ::: "memory");
}
__device__ __forceinline__ void cpa_wait0() {
    asm volatile("cp.async.wait_group 0;" ::: "memory");
}
__device__ __forceinline__ void mma8(float* c, const uint32_t* a, uint32_t b0, uint32_t b1) {
    asm volatile(
        "mma.sync.aligned.m16n8k8.row.col.f32.tf32.tf32.f32 "
        "{%0,%1,%2,%3},{%4,%5,%6,%7},{%8,%9},{%0,%1,%2,%3};"
        : "+f"(c[0]), "+f"(c[1]), "+f"(c[2]), "+f"(c[3])
        : "r"(a[0]), "r"(a[1]), "r"(a[2]), "r"(a[3]), "r"(b0), "r"(b1));
}

// ---------------- K0: global average pool ----------------
__global__ void k_gap(const float* __restrict__ x) {
    int bc = blockIdx.x;
    const float* p = x + (size_t)bc * PIX;
    float s = 0.f;
    for (int i = threadIdx.x; i < PIX; i += 256) s += p[i];
    __shared__ float red[8];
    #pragma unroll
    for (int o = 16; o; o >>= 1) s += __shfl_down_sync(0xffffffffu, s, o);
    if ((threadIdx.x & 31) == 0) red[threadIdx.x >> 5] = s;
    __syncthreads();
    if (threadIdx.x < 8) {
        s = red[threadIdx.x];
        #pragma unroll
        for (int o = 4; o; o >>= 1) s += __shfl_down_sync(0xffu, s, o);
        if (threadIdx.x == 0) g_xgap[bc >> 7][bc & 127] = s * (1.0f / PIX);
    }
}

// ---------------- K1: gating, top-2, combine weights, loss ----------------
__global__ void k_gate(const float* __restrict__ G, const float* __restrict__ bp,
                       float* __restrict__ dout) {
    __shared__ float probs[BB][EE];
    __shared__ float losses[NG];
    int t = threadIdx.x;
    if (t < EE * BB) g_mask[t / BB][t % BB] = 0;
    __syncthreads();
    for (int g = 0; g < NG; g++) {
        if (t < BB * EE) {
            int b = t >> 3, e = t & 7;
            float s = 0.f;
            for (int c = 0; c < CC; c++) s += g_xgap[b][c] * G[(g * CC + c) * EE + e];
            probs[b][e] = s;
        }
        __syncthreads();
        if (t < BB) {
            int b = t;
            float mx = probs[b][0];
            #pragma unroll
            for (int e = 1; e < EE; e++) mx = fmaxf(mx, probs[b][e]);
            float pr[EE]; float sum = 0.f;
            #pragma unroll
            for (int e = 0; e < EE; e++) { pr[e] = expf(probs[b][e] - mx); sum += pr[e]; }
            float inv = 1.f / sum;
            #pragma unroll
            for (int e = 0; e < EE; e++) { pr[e] *= inv; probs[b][e] = pr[e]; }
            int i0 = 0;
            #pragma unroll
            for (int e = 1; e < EE; e++) if (pr[e] > pr[i0]) i0 = e;
            int i1 = (i0 == 0) ? 1 : 0;
            #pragma unroll
            for (int e = 0; e < EE; e++) if (e != i0 && pr[e] > pr[i1]) i1 = e;
            float e1 = expf(pr[i1] - pr[i0]);
            float tw0 = 1.f / (1.f + e1), tw1 = e1 / (1.f + e1);
            #pragma unroll
            for (int e = 0; e < EE; e++) g_wt[g][b][e] = 0.f;
            g_wt[g][b][i0] = tw0; g_wt[g][b][i1] = tw1;
            g_sel[g][b][0] = i0; g_sel[g][b][1] = i1;
            g_mask[i0][b] = 1; g_mask[i1][b] = 1;
        }
        __syncthreads();
        if (t == 0) {
            float v[EE]; float mean = 0.f;
            #pragma unroll
            for (int e = 0; e < EE; e++) {
                float s = 0.f;
                for (int b = 0; b < BB; b++) s += probs[b][e];
                v[e] = s; mean += s;
            }
            mean *= (1.0f / EE);
            float var = 0.f;
            #pragma unroll
            for (int e = 0; e < EE; e++) { float d = v[e] - mean; var += d * d; }
            var *= (1.0f / (EE - 1));
            losses[g] = var / (mean * mean + 1e-10f);
        }
        __syncthreads();
    }
    if (t < CC) {
        for (int g = 0; g < NG; g++)
            for (int b = 0; b < BB; b++) {
                float s = 0.f;
                #pragma unroll
                for (int e = 0; e < EE; e++) s += g_wt[g][b][e] * bp[e * CC + t];
                g_beff[g][b][t] = s;
            }
    }
    if (t == 0)
        dout[(size_t)NG * BB * CC * PIX] =
            0.25f * (losses[0] + losses[1] + losses[2] + losses[3]);
}

// ---------------- pack x -> padded pixel-major tf32 planes ----------------
__global__ void k_packx(const float* __restrict__ x) {
    int b = blockIdx.y, p0 = blockIdx.x * 64;
    __shared__ float sx[128][65];
    int t = threadIdx.x;
    for (int i = t; i < 8192; i += 256) {
        int ci = i >> 6, p = i & 63;
        sx[ci][p] = x[((size_t)b * CC + ci) * PIX + p0 + p];
    }
    __syncthreads();
    for (int i = t; i < 2048; i += 256) {
        int p = i >> 5, c = (i >> 3) & 3, q = i & 7;
        int dp = p0 + p, h = dp / 96, w = dp % 96;
        int pp = (h + 1) * 98 + (w + 1) + 128;
        uint4 v;
        v.x = f2tf32(sx[c * 32 + q * 4 + 0][p]);
        v.y = f2tf32(sx[c * 32 + q * 4 + 1][p]);
        v.z = f2tf32(sx[c * 32 + q * 4 + 2][p]);
        v.w = f2tf32(sx[c * 32 + q * 4 + 3][p]);
        *(uint4*)&g_xt[(((size_t)b * 4 + c) * XROWS + pp) * 32 + q * 4] = v;
    }
}

// ---------------- pack conv weights: [e,tap,chunk][ci32][co128] ----------------
__global__ void k_packw(const float* __restrict__ Wc) {
    int idx = blockIdx.x * 256 + threadIdx.x;
    int c4 = idx & 31, ci = (idx >> 5) & 31, c = (idx >> 10) & 3;
    int et = idx >> 12, tap = et % 9, e = et / 9;
    int co = c4 * 4;
    const float* s = Wc + (((size_t)(e * CC + co) * CC + c * 32 + ci) * 9 + tap);
    uint4 v;
    v.x = f2tf32(s[0]);
    v.y = f2tf32(s[1152]);
    v.z = f2tf32(s[2304]);
    v.w = f2tf32(s[3456]);
    ((uint4*)g_wtb)[idx] = v;
}

// ---------------- pack gate-scaled pw weights: [g,b,slot][ci128][co128] ----------------
__global__ void k_packbp(const float* __restrict__ Wp) {
    int idx = blockIdx.x * 256 + threadIdx.x;
    int c4 = idx & 31, ci = (idx >> 5) & 127, slot = (idx >> 12) & 1;
    int b = (idx >> 13) & 7, g = idx >> 16;
    int e = g_sel[g][b][slot];
    float wv = g_wt[g][b][e];
    int co = c4 * 4;
    const float* s = Wp + (size_t)e * CC * CC + (size_t)co * CC + ci;
    uint4 v;
    v.x = f2tf32(s[0]   * wv);
    v.y = f2tf32(s[128] * wv);
    v.z = f2tf32(s[256] * wv);
    v.w = f2tf32(s[384] * wv);
    ((uint4*)g_bp)[idx] = v;
}

// ---------------- conv: M=256 tile, cp.async pipelined, fused bias/relu/squash ------
// 8 warps: wm = wid&3 (64 rows each), wn = wid>>2 (64 cols each); warp tile 64x64.
#define XS_W 36
#define WS_W 136
#define XS_SZ 16344              // 454*36
#define CV_XS0 0
#define CV_XS1 16344
#define CV_WS0 32688             // 4352 each
#define CV_WS1 37040
#define CV_WS2A 41392
#define CV_WS2B 45744
#define CV_BIAS 50096
#define CV_SS   50224
#define CV_SMEMB ((50224 + 256) * 4)   // 201,920 B

__global__ void __launch_bounds__(256) k_conv_mma(const float* __restrict__ bc) {
    int e = blockIdx.z, b = blockIdx.y;
    if (!g_mask[e][b]) return;
    extern __shared__ uint32_t S[];
    float* bias = (float*)(S + CV_BIAS);
    float* ssm  = (float*)(S + CV_SS);
    int t = threadIdx.x, lane = t & 31, wid = t >> 5;
    int wm = wid & 3, wn = wid >> 2;
    int gp = lane >> 2, tg = lane & 3;
    int q0 = blockIdx.x * 256;
    uint32_t sbase = smem_u32(S);
    ssm[t] = 0.f;
    if (t < 128) bias[t] = bc[e * CC + t];

    float acc[4][8][4];
    #pragma unroll
    for (int mt = 0; mt < 4; mt++)
        #pragma unroll
        for (int nt = 0; nt < 8; nt++)
            #pragma unroll
            for (int k = 0; k < 4; k++) acc[mt][nt][k] = 0.f;
    const int drow[9] = {0, 1, 2, 98, 99, 100, 196, 197, 198};

    // prologue: chunk0 x tile + chunk0 tap0 weights
    {
        const uint4* xsrc = (const uint4*)(g_xt + (((size_t)b * 4 + 0) * XROWS + q0 + 29) * 32);
        for (int i = t; i < 3632; i += 256) {
            int r = i >> 3, q = i & 7;
            cpa16(sbase + (CV_XS0 + r * XS_W + q * 4) * 4, xsrc + i);
        }
        const uint4* wsrc = (const uint4*)(g_wtb + ((size_t)((e * 9 + 0) * 4 + 0)) * 4096);
        for (int i = t; i < 1024; i += 256) {
            int ci = i >> 5, c4 = i & 31;
            cpa16(sbase + (CV_WS2A + ci * WS_W + c4 * 4) * 4, wsrc + i);
        }
        cpa_commit();
    }

    for (int c = 0; c < 4; c++) {
        if (c < 3) {
            int cn = c + 1;
            uint32_t xoff = (cn & 1) ? CV_XS1 : CV_XS0;
            const uint4* xsrc = (const uint4*)(g_xt + (((size_t)b * 4 + cn) * XROWS + q0 + 29) * 32);
            for (int i = t; i < 3632; i += 256) {
                int r = i >> 3, q = i & 7;
                cpa16(sbase + (xoff + r * XS_W + q * 4) * 4, xsrc + i);
            }
            uint32_t w2off = (cn & 1) ? CV_WS2B : CV_WS2A;
            const uint4* wsrc = (const uint4*)(g_wtb + ((size_t)((e * 9 + 0) * 4 + cn)) * 4096);
            for (int i = t; i < 1024; i += 256) {
                int ci = i >> 5, c4 = i & 31;
                cpa16(sbase + (w2off + ci * WS_W + c4 * 4) * 4, wsrc + i);
            }
            cpa_commit();
            cpa_wait1();
        } else {
            cpa_wait0();
        }
        __syncthreads();
        const uint32_t* xsb = S + ((c & 1) ? CV_XS1 : CV_XS0);

        for (int tap = 0; tap < 9; tap++) {
            const uint32_t* wb = (tap == 0)
                ? (S + ((c & 1) ? CV_WS2B : CV_WS2A))
                : (S + (((tap - 1) & 1) ? CV_WS1 : CV_WS0));
            uint4 pf[4];
            bool hp = (tap < 8);
            if (hp) {
                const uint4* wsrc = (const uint4*)(g_wtb + ((size_t)((e * 9 + tap + 1) * 4 + c)) * 4096);
                #pragma unroll
                for (int j = 0; j < 4; j++) pf[j] = wsrc[t + j * 256];
            }
            int rb = wm * 64 + gp + drow[tap];
            #pragma unroll
            for (int k8 = 0; k8 < 4; k8++) {
                int k0 = k8 * 8 + tg;
                uint32_t a[4][4];
                #pragma unroll
                for (int mt = 0; mt < 4; mt++) {
                    const uint32_t* xp = xsb + (rb + mt * 16) * XS_W;
                    a[mt][0] = xp[k0];
                    a[mt][1] = xp[8 * XS_W + k0];
                    a[mt][2] = xp[k0 + 4];
                    a[mt][3] = xp[8 * XS_W + k0 + 4];
                }
                #pragma unroll
                for (int nt = 0; nt < 8; nt++) {
                    int n = wn * 64 + nt * 8 + gp;
                    uint32_t b0 = wb[k0 * WS_W + n];
                    uint32_t b1 = wb[(k0 + 4) * WS_W + n];
                    #pragma unroll
                    for (int mt = 0; mt < 4; mt++) mma8(acc[mt][nt], a[mt], b0, b1);
                }
            }
            if (hp) {
                uint32_t* wd = S + ((tap & 1) ? CV_WS1 : CV_WS0);
                #pragma unroll
                for (int j = 0; j < 4; j++) {
                    int i = t + j * 256;
                    int ci = i >> 5, c4 = i & 31;
                    *(uint4*)&wd[ci * WS_W + c4 * 4] = pf[j];
                }
            }
            __syncthreads();
        }
    }

    // epilogue: bias + relu + per-pixel squash + tf32 store
    float ssq[4][2];
    #pragma unroll
    for (int mt = 0; mt < 4; mt++) { ssq[mt][0] = 0.f; ssq[mt][1] = 0.f; }
    #pragma unroll
    for (int mt = 0; mt < 4; mt++)
        #pragma unroll
        for (int nt = 0; nt < 8; nt++)
            #pragma unroll
            for (int k = 0; k < 4; k++) {
                int col = wn * 64 + nt * 8 + 2 * tg + (k & 1);
                float v = fmaxf(acc[mt][nt][k] + bias[col], 0.f);
                acc[mt][nt][k] = v;
                ssq[mt][k >> 1] += v * v;
            }
    #pragma unroll
    for (int mt = 0; mt < 4; mt++)
        #pragma unroll
        for (int h = 0; h < 2; h++) {
            float s = ssq[mt][h];
            s += __shfl_xor_sync(0xffffffffu, s, 1);
            s += __shfl_xor_sync(0xffffffffu, s, 2);
            if (tg == 0) atomicAdd(&ssm[wm * 64 + mt * 16 + gp + 8 * h], s);
        }
    __syncthreads();
    uint32_t* up = g_ub + (size_t)(e * BB + b) * UROWS * CC;
    #pragma unroll
    for (int mt = 0; mt < 4; mt++)
        #pragma unroll
        for (int h = 0; h < 2; h++) {
            int r = wm * 64 + mt * 16 + gp + 8 * h;
            int q = q0 + r;
            if (q < UROWS) {
                float s = ssm[r];
                float sc = s / (1.f + s) * rsqrtf(s + 1e-8f);
                #pragma unroll
                for (int nt = 0; nt < 8; nt++) {
                    uint2 v;
                    v.x = f2tf32(acc[mt][nt][h * 2] * sc);
                    v.y = f2tf32(acc[mt][nt][h * 2 + 1] * sc);
                    *(uint2*)&up[(size_t)q * CC + wn * 64 + nt * 8 + 2 * tg] = v;
                }
            }
        }
}

// ---------------- pw: per-(gate,b) K-stacked GEMM, cp.async double-buffered ---------
#define PW_US0 0
#define PW_US1 4608
#define PW_WS0 9216
#define PW_WS1 13568
#define PW_BIAS 17920
#define PW_SMEMB ((17920 + 128) * 4)   // 72,192 B

__global__ void __launch_bounds__(256) k_pw_mma(float* __restrict__ out) {
    int g = blockIdx.z, b = blockIdx.y, q0 = blockIdx.x * 128;
    extern __shared__ uint32_t S[];
    float* bias = (float*)(S + PW_BIAS);
    int t = threadIdx.x, lane = t & 31, wid = t >> 5;
    int wm = wid & 3, wn = wid >> 2;
    int gp = lane >> 2, tg = lane & 3;
    uint32_t sbase = smem_u32(S);
    if (t < 128) bias[t] = g_beff[g][b][t];
    float acc[2][8][4];
    #pragma unroll
    for (int mt = 0; mt < 2; mt++)
        #pragma unroll
        for (int nt = 0; nt < 8; nt++)
            #pragma unroll
            for (int k = 0; k < 4; k++) acc[mt][nt][k] = 0.f;

    // issue helper inlined: group = {u tile, w tile} for chunk kc into buf parity
    {
        int e = g_sel[g][b][0];
        const uint4* usrc = (const uint4*)(g_ub + ((size_t)(e * BB + b) * UROWS + q0) * CC);
        for (int i = t; i < 1024; i += 256) {
            int r = i >> 3, q = i & 7;
            cpa16(sbase + (PW_US0 + r * XS_W + q * 4) * 4, usrc + (size_t)r * 32 + q);
        }
        const uint4* wsrc = (const uint4*)(g_bp + ((size_t)((g * BB + b) * 2 + 0)) * CC * CC);
        for (int i = t; i < 1024; i += 256) {
            int ci = i >> 5, c4 = i & 31;
            cpa16(sbase + (PW_WS0 + ci * WS_W + c4 * 4) * 4, wsrc + i);
        }
        cpa_commit();
    }

    for (int kc = 0; kc < 8; kc++) {
        if (kc < 7) {
            int kn = kc + 1, slot = kn >> 2, c = kn & 3;
            int e = g_sel[g][b][slot];
            uint32_t uoff = (kn & 1) ? PW_US1 : PW_US0;
            uint32_t woff = (kn & 1) ? PW_WS1 : PW_WS0;
            const uint4* usrc = (const uint4*)(g_ub + ((size_t)(e * BB + b) * UROWS + q0) * CC + c * 32);
            for (int i = t; i < 1024; i += 256) {
                int r = i >> 3, q = i & 7;
                cpa16(sbase + (uoff + r * XS_W + q * 4) * 4, usrc + (size_t)r * 32 + q);
            }
            const uint4* wsrc = (const uint4*)(g_bp + ((size_t)((g * BB + b) * 2 + slot)) * CC * CC
                                               + (size_t)c * 32 * CC);
            for (int i = t; i < 1024; i += 256) {
                int ci = i >> 5, c4 = i & 31;
                cpa16(sbase + (woff + ci * WS_W + c4 * 4) * 4, wsrc + i);
            }
            cpa_commit();
            cpa_wait1();
        } else {
            cpa_wait0();
        }
        __syncthreads();
        const uint32_t* us = S + ((kc & 1) ? PW_US1 : PW_US0);
        const uint32_t* ws = S + ((kc & 1) ? PW_WS1 : PW_WS0);
        int rb = wm * 32 + gp;
        #pragma unroll
        for (int k8 = 0; k8 < 4; k8++) {
            int k0 = k8 * 8 + tg;
            uint32_t a[2][4];
            #pragma unroll
            for (int mt = 0; mt < 2; mt++) {
                const uint32_t* xp = us + (rb + mt * 16) * XS_W;
                a[mt][0] = xp[k0];
                a[mt][1] = xp[8 * XS_W + k0];
                a[mt][2] = xp[k0 + 4];
                a[mt][3] = xp[8 * XS_W + k0 + 4];
            }
            #pragma unroll
            for (int nt = 0; nt < 8; nt++) {
                int n = wn * 64 + nt * 8 + gp;
                uint32_t b0 = ws[k0 * WS_W + n];
                uint32_t b1 = ws[(k0 + 4) * WS_W + n];
                mma8(acc[0][nt], a[0], b0, b1);
                mma8(acc[1][nt], a[1], b0, b1);
            }
        }
        __syncthreads();
    }
    // epilogue: + bias, map padded pixel -> (h,w), write valid
    #pragma unroll
    for (int mt = 0; mt < 2; mt++)
        #pragma unroll
        for (int k = 0; k < 4; k++) {
            int r = wm * 32 + mt * 16 + gp + 8 * (k >> 1);
            int q = q0 + r;
            int h = q / 98 - 1, w = q % 98 - 1;
            if ((unsigned)h < 96u && (unsigned)w < 96u) {
                #pragma unroll
                for (int nt = 0; nt < 8; nt++) {
                    int col = wn * 64 + nt * 8 + 2 * tg + (k & 1);
                    out[(((size_t)g * BB + b) * CC + col) * PIX + h * 96 + w] =
                        acc[mt][nt][k] + bias[col];
                }
            }
        }
}

// ---------------- launch ----------------
extern "C" void kernel_launch(void* const* d_in, const int* in_sizes, int n_in,
                              void* d_out, int out_size) {
    const float* x  = (const float*)d_in[0];
    const float* G  = (const float*)d_in[1];
    const float* Wc = (const float*)d_in[2];
    const float* bc = (const float*)d_in[3];
    const float* Wp = (const float*)d_in[4];
    const float* bp = (const float*)d_in[5];
    float* out = (float*)d_out;

    cudaFuncSetAttribute(k_conv_mma, cudaFuncAttributeMaxDynamicSharedMemorySize, CV_SMEMB);
    cudaFuncSetAttribute(k_pw_mma,   cudaFuncAttributeMaxDynamicSharedMemorySize, PW_SMEMB);

    k_gap<<<BB * CC, 256>>>(x);
    k_gate<<<1, 128>>>(G, bp, out);
    k_packx<<<dim3(144, BB), 256>>>(x);
    k_packw<<<1152, 256>>>(Wc);
    k_packbp<<<1024, 256>>>(Wp);
    k_conv_mma<<<dim3(NT2, BB, EE), 256, CV_SMEMB>>>(bc);
    k_pw_mma<<<dim3(NTT, BB, NG), 256, PW_SMEMB>>>(out);
}

// round 10
// speedup vs baseline: 6.2967x; 1.5367x over previous
#include <cuda_runtime.h>
#include <cuda_fp16.h>
#include <math.h>
#include <stdint.h>

#define BB 8
#define CC 128
#define EE 8
#define NG 4
#define PIX 9216
#define XROWS 10240     // x plane rows: 128 lead pad + pp + slack
#define NTT 75          // pw M-tiles of 128 padded pixels
#define NT2 38          // conv M-tiles of 256 padded pixels
#define UROWS 9600

// ---------------- device globals ----------------
__device__ float g_xgap[BB][CC];
__device__ float g_wt[NG][BB][EE];
__device__ int   g_sel[NG][BB][2];
__device__ int   g_mask[EE][BB];
__device__ float g_beff[NG][BB][CC];
__device__ uint32_t g_xt[(size_t)BB*4*XROWS*16];      // fp16 x, [b][chunk][row][32ci halves]
__device__ uint32_t g_wtb[(size_t)EE*9*4*CC*16];      // fp16 conv W, [e,tap,chunk][co][32ci halves]
__device__ uint32_t g_bp[(size_t)NG*BB*2*CC*64];      // fp16 gate-scaled pw W, [g,b,slot][co][128ci halves]
__device__ uint32_t g_ub[(size_t)EE*BB*UROWS*64];     // fp16 squashed u, [pair][row][128ci halves]

// ---------------- helpers ----------------
__device__ __forceinline__ uint32_t f2h2(float lo, float hi) {
    uint32_t r;
    asm("cvt.rn.f16x2.f32 %0, %1, %2;" : "=r"(r) : "f"(hi), "f"(lo));
    return r;
}
__device__ __forceinline__ uint32_t smem_u32(const void* p) {
    uint32_t a;
    asm("{ .reg .u64 t; cvta.to.shared.u64 t, %1; cvt.u32.u64 %0, t; }" : "=r"(a) : "l"(p));
    return a;
}
__device__ __forceinline__ void cpa16(uint32_t dst, const void* src) {
    asm volatile("cp.async.cg.shared.global [%0], [%1], 16;" :: "r"(dst), "l"(src) : "memory");
}
__device__ __forceinline__ void cpa_commit() {
    asm volatile("cp.async.commit_group;" ::: "memory");
}
__device__ __forceinline__ void cpa_wait1() {
    asm volatile("cp.async.wait_group 1;" ::: "memory");
}
__device__ __forceinline__ void cpa_wait0() {
    asm volatile("cp.async.wait_group 0;" ::: "memory");
}
__device__ __forceinline__ void mma16(float* c, const uint32_t* a, uint32_t b0, uint32_t b1) {
    asm volatile(
        "mma.sync.aligned.m16n8k16.row.col.f32.f16.f16.f32 "
        "{%0,%1,%2,%3},{%4,%5,%6,%7},{%8,%9},{%0,%1,%2,%3};"
        : "+f"(c[0]), "+f"(c[1]), "+f"(c[2]), "+f"(c[3])
        : "r"(a[0]), "r"(a[1]), "r"(a[2]), "r"(a[3]), "r"(b0), "r"(b1));
}

// ---------------- K0: global average pool ----------------
__global__ void k_gap(const float* __restrict__ x) {
    int bc = blockIdx.x;
    const float* p = x + (size_t)bc * PIX;
    float s = 0.f;
    for (int i = threadIdx.x; i < PIX; i += 256) s += p[i];
    __shared__ float red[8];
    #pragma unroll
    for (int o = 16; o; o >>= 1) s += __shfl_down_sync(0xffffffffu, s, o);
    if ((threadIdx.x & 31) == 0) red[threadIdx.x >> 5] = s;
    __syncthreads();
    if (threadIdx.x < 8) {
        s = red[threadIdx.x];
        #pragma unroll
        for (int o = 4; o; o >>= 1) s += __shfl_down_sync(0xffu, s, o);
        if (threadIdx.x == 0) g_xgap[bc >> 7][bc & 127] = s * (1.0f / PIX);
    }
}

// ---------------- K1: gating, top-2, combine weights, loss ----------------
__global__ void k_gate(const float* __restrict__ G, const float* __restrict__ bp,
                       float* __restrict__ dout) {
    __shared__ float probs[BB][EE];
    __shared__ float losses[NG];
    int t = threadIdx.x;
    if (t < EE * BB) g_mask[t / BB][t % BB] = 0;
    __syncthreads();
    for (int g = 0; g < NG; g++) {
        if (t < BB * EE) {
            int b = t >> 3, e = t & 7;
            float s = 0.f;
            for (int c = 0; c < CC; c++) s += g_xgap[b][c] * G[(g * CC + c) * EE + e];
            probs[b][e] = s;
        }
        __syncthreads();
        if (t < BB) {
            int b = t;
            float mx = probs[b][0];
            #pragma unroll
            for (int e = 1; e < EE; e++) mx = fmaxf(mx, probs[b][e]);
            float pr[EE]; float sum = 0.f;
            #pragma unroll
            for (int e = 0; e < EE; e++) { pr[e] = expf(probs[b][e] - mx); sum += pr[e]; }
            float inv = 1.f / sum;
            #pragma unroll
            for (int e = 0; e < EE; e++) { pr[e] *= inv; probs[b][e] = pr[e]; }
            int i0 = 0;
            #pragma unroll
            for (int e = 1; e < EE; e++) if (pr[e] > pr[i0]) i0 = e;
            int i1 = (i0 == 0) ? 1 : 0;
            #pragma unroll
            for (int e = 0; e < EE; e++) if (e != i0 && pr[e] > pr[i1]) i1 = e;
            float e1 = expf(pr[i1] - pr[i0]);
            float tw0 = 1.f / (1.f + e1), tw1 = e1 / (1.f + e1);
            #pragma unroll
            for (int e = 0; e < EE; e++) g_wt[g][b][e] = 0.f;
            g_wt[g][b][i0] = tw0; g_wt[g][b][i1] = tw1;
            g_sel[g][b][0] = i0; g_sel[g][b][1] = i1;
            g_mask[i0][b] = 1; g_mask[i1][b] = 1;
        }
        __syncthreads();
        if (t == 0) {
            float v[EE]; float mean = 0.f;
            #pragma unroll
            for (int e = 0; e < EE; e++) {
                float s = 0.f;
                for (int b = 0; b < BB; b++) s += probs[b][e];
                v[e] = s; mean += s;
            }
            mean *= (1.0f / EE);
            float var = 0.f;
            #pragma unroll
            for (int e = 0; e < EE; e++) { float d = v[e] - mean; var += d * d; }
            var *= (1.0f / (EE - 1));
            losses[g] = var / (mean * mean + 1e-10f);
        }
        __syncthreads();
    }
    if (t < CC) {
        for (int g = 0; g < NG; g++)
            for (int b = 0; b < BB; b++) {
                float s = 0.f;
                #pragma unroll
                for (int e = 0; e < EE; e++) s += g_wt[g][b][e] * bp[e * CC + t];
                g_beff[g][b][t] = s;
            }
    }
    if (t == 0)
        dout[(size_t)NG * BB * CC * PIX] =
            0.25f * (losses[0] + losses[1] + losses[2] + losses[3]);
}

// ---------------- pack x -> padded pixel-major fp16 planes ----------------
__global__ void k_packx(const float* __restrict__ x) {
    int b = blockIdx.y, p0 = blockIdx.x * 64;
    __shared__ float sx[128][65];
    int t = threadIdx.x;
    for (int i = t; i < 8192; i += 256) {
        int ci = i >> 6, p = i & 63;
        sx[ci][p] = x[((size_t)b * CC + ci) * PIX + p0 + p];
    }
    __syncthreads();
    for (int i = t; i < 1024; i += 256) {
        int p = i >> 4, c = (i >> 2) & 3, q = i & 3;
        int dp = p0 + p, h = dp / 96, w = dp % 96;
        int pp = (h + 1) * 98 + (w + 1) + 128;
        int ci0 = c * 32 + q * 8;
        uint4 v;
        v.x = f2h2(sx[ci0 + 0][p], sx[ci0 + 1][p]);
        v.y = f2h2(sx[ci0 + 2][p], sx[ci0 + 3][p]);
        v.z = f2h2(sx[ci0 + 4][p], sx[ci0 + 5][p]);
        v.w = f2h2(sx[ci0 + 6][p], sx[ci0 + 7][p]);
        ((uint4*)g_xt)[((size_t)(b * 4 + c) * XROWS + pp) * 4 + q] = v;
    }
}

// ---------------- pack conv weights: [e,tap,chunk][co][32ci halves] ----------------
__global__ void k_packw(const float* __restrict__ Wc) {
    int idx = blockIdx.x * 256 + threadIdx.x;      // 147456 uint4
    int q = idx & 3, co = (idx >> 2) & 127, c = (idx >> 9) & 3;
    int et = idx >> 11, tap = et % 9, e = et / 9;
    const float* s = Wc + (((size_t)(e * CC + co) * CC + c * 32 + q * 8) * 9 + tap);
    uint4 v;
    v.x = f2h2(s[0],  s[9]);
    v.y = f2h2(s[18], s[27]);
    v.z = f2h2(s[36], s[45]);
    v.w = f2h2(s[54], s[63]);
    ((uint4*)g_wtb)[idx] = v;
}

// ---------------- pack gate-scaled pw weights: [g,b,slot][co][128ci halves] ------------
__global__ void k_packbp(const float* __restrict__ Wp) {
    int idx = blockIdx.x * 256 + threadIdx.x;      // 131072 uint4
    int q = idx & 15, co = (idx >> 4) & 127, slot = (idx >> 11) & 1;
    int b = (idx >> 12) & 7, g = idx >> 15;
    int e = g_sel[g][b][slot];
    float wv = g_wt[g][b][e];
    const float* s = Wp + (size_t)e * CC * CC + (size_t)co * CC + q * 8;
    uint4 v;
    v.x = f2h2(s[0] * wv, s[1] * wv);
    v.y = f2h2(s[2] * wv, s[3] * wv);
    v.z = f2h2(s[4] * wv, s[5] * wv);
    v.w = f2h2(s[6] * wv, s[7] * wv);
    ((uint4*)g_bp)[idx] = v;
}

// ---------------- conv: fp16 m16n8k16, M=256 tile, cp.async pipelined ----------------
// 8 warps: wm = wid&3 (64 rows), wn = wid>>2 (64 cols); warp tile 64x64.
// smem word offsets (stride 20 words = 40 halves per row, conflict-free)
#define CV_XS0 0
#define CV_XS1 9080              // 454*20
#define CV_WSA 18160             // 128*20 each
#define CV_WSB 20720
#define CV_W2A 23280
#define CV_W2B 25840
#define CV_BIAS 28400
#define CV_SS   28528
#define CV_SMEMB ((28528 + 256) * 4)   // 115,136 B

__global__ void __launch_bounds__(256) k_conv_mma(const float* __restrict__ bc) {
    int e = blockIdx.z, b = blockIdx.y;
    if (!g_mask[e][b]) return;
    extern __shared__ uint32_t S[];
    float* bias = (float*)(S + CV_BIAS);
    float* ssm  = (float*)(S + CV_SS);
    int t = threadIdx.x, lane = t & 31, wid = t >> 5;
    int wm = wid & 3, wn = wid >> 2;
    int gp = lane >> 2, tg = lane & 3;
    int q0 = blockIdx.x * 256;
    uint32_t sbase = smem_u32(S);
    ssm[t] = 0.f;
    if (t < 128) bias[t] = bc[e * CC + t];

    float acc[4][8][4];
    #pragma unroll
    for (int mt = 0; mt < 4; mt++)
        #pragma unroll
        for (int nt = 0; nt < 8; nt++)
            #pragma unroll
            for (int k = 0; k < 4; k++) acc[mt][nt][k] = 0.f;
    const int drow[9] = {0, 1, 2, 98, 99, 100, 196, 197, 198};

    // prologue: chunk0 x tile + chunk0 tap0 weights
    {
        const uint4* xsrc = (const uint4*)g_xt + ((size_t)(b * 4 + 0) * XROWS + q0 + 29) * 4;
        for (int i = t; i < 1816; i += 256) {
            int r = i >> 2, q = i & 3;
            cpa16(sbase + (CV_XS0 + r * 20 + q * 4) * 4, xsrc + i);
        }
        const uint4* wsrc = (const uint4*)g_wtb + (size_t)((e * 9 + 0) * 4 + 0) * 512;
        for (int i = t; i < 512; i += 256) {
            int co = i >> 2, q = i & 3;
            cpa16(sbase + (CV_W2A + co * 20 + q * 4) * 4, wsrc + i);
        }
        cpa_commit();
    }

    for (int c = 0; c < 4; c++) {
        if (c < 3) {
            int cn = c + 1;
            uint32_t xoff = (cn & 1) ? CV_XS1 : CV_XS0;
            const uint4* xsrc = (const uint4*)g_xt + ((size_t)(b * 4 + cn) * XROWS + q0 + 29) * 4;
            for (int i = t; i < 1816; i += 256) {
                int r = i >> 2, q = i & 3;
                cpa16(sbase + (xoff + r * 20 + q * 4) * 4, xsrc + i);
            }
            uint32_t w2off = (cn & 1) ? CV_W2B : CV_W2A;
            const uint4* wsrc = (const uint4*)g_wtb + (size_t)((e * 9 + 0) * 4 + cn) * 512;
            for (int i = t; i < 512; i += 256) {
                int co = i >> 2, q = i & 3;
                cpa16(sbase + (w2off + co * 20 + q * 4) * 4, wsrc + i);
            }
            cpa_commit();
            cpa_wait1();
        } else {
            cpa_wait0();
        }
        __syncthreads();
        const uint32_t* xsb = S + ((c & 1) ? CV_XS1 : CV_XS0);

        for (int tap = 0; tap < 9; tap++) {
            const uint32_t* wb = (tap == 0)
                ? (S + ((c & 1) ? CV_W2B : CV_W2A))
                : (S + (((tap - 1) & 1) ? CV_WSB : CV_WSA));
            uint4 pf[2];
            bool hp = (tap < 8);
            if (hp) {
                const uint4* wsrc = (const uint4*)g_wtb + (size_t)((e * 9 + tap + 1) * 4 + c) * 512;
                pf[0] = wsrc[t];
                pf[1] = wsrc[t + 256];
            }
            int rb = wm * 64 + gp + drow[tap];
            #pragma unroll
            for (int ks = 0; ks < 2; ks++) {
                int k0 = ks * 8 + tg;
                uint32_t a[4][4];
                #pragma unroll
                for (int mt = 0; mt < 4; mt++) {
                    const uint32_t* xp = xsb + (rb + mt * 16) * 20;
                    a[mt][0] = xp[k0];
                    a[mt][1] = xp[160 + k0];
                    a[mt][2] = xp[k0 + 4];
                    a[mt][3] = xp[160 + k0 + 4];
                }
                #pragma unroll
                for (int nt = 0; nt < 8; nt++) {
                    int n = wn * 64 + nt * 8 + gp;
                    uint32_t b0 = wb[n * 20 + k0];
                    uint32_t b1 = wb[n * 20 + k0 + 4];
                    #pragma unroll
                    for (int mt = 0; mt < 4; mt++) mma16(acc[mt][nt], a[mt], b0, b1);
                }
            }
            if (hp) {
                uint32_t* wd = S + ((tap & 1) ? CV_WSB : CV_WSA);
                {
                    int co = t >> 2, q = t & 3;
                    *(uint4*)&wd[co * 20 + q * 4] = pf[0];
                    int i = t + 256;
                    co = i >> 2; q = i & 3;
                    *(uint4*)&wd[co * 20 + q * 4] = pf[1];
                }
            }
            __syncthreads();
        }
    }

    // epilogue: bias + relu + per-pixel squash + fp16 store
    float ssq[4][2];
    #pragma unroll
    for (int mt = 0; mt < 4; mt++) { ssq[mt][0] = 0.f; ssq[mt][1] = 0.f; }
    #pragma unroll
    for (int mt = 0; mt < 4; mt++)
        #pragma unroll
        for (int nt = 0; nt < 8; nt++)
            #pragma unroll
            for (int k = 0; k < 4; k++) {
                int col = wn * 64 + nt * 8 + 2 * tg + (k & 1);
                float v = fmaxf(acc[mt][nt][k] + bias[col], 0.f);
                acc[mt][nt][k] = v;
                ssq[mt][k >> 1] += v * v;
            }
    #pragma unroll
    for (int mt = 0; mt < 4; mt++)
        #pragma unroll
        for (int h = 0; h < 2; h++) {
            float s = ssq[mt][h];
            s += __shfl_xor_sync(0xffffffffu, s, 1);
            s += __shfl_xor_sync(0xffffffffu, s, 2);
            if (tg == 0) atomicAdd(&ssm[wm * 64 + mt * 16 + gp + 8 * h], s);
        }
    __syncthreads();
    uint32_t* up = g_ub + (size_t)(e * BB + b) * UROWS * 64;
    #pragma unroll
    for (int mt = 0; mt < 4; mt++)
        #pragma unroll
        for (int h = 0; h < 2; h++) {
            int r = wm * 64 + mt * 16 + gp + 8 * h;
            int q = q0 + r;
            if (q < UROWS) {
                float s = ssm[r];
                float sc = s / (1.f + s) * rsqrtf(s + 1e-8f);
                #pragma unroll
                for (int nt = 0; nt < 8; nt++) {
                    up[(size_t)q * 64 + wn * 32 + nt * 4 + tg] =
                        f2h2(acc[mt][nt][h * 2] * sc, acc[mt][nt][h * 2 + 1] * sc);
                }
            }
        }
}

// ---------------- pw: fp16 K-stacked GEMM + smem-transposed coalesced store ----------
#define PW_US0 0
#define PW_US1 2560
#define PW_WS0 5120
#define PW_WS1 7680
#define PW_BIAS 16896            // stage[128][132] floats reuses words 0..16895
#define PW_SMEMB ((16896 + 128) * 4)   // 68,096 B

__global__ void __launch_bounds__(256) k_pw_mma(float* __restrict__ out) {
    int g = blockIdx.z, b = blockIdx.y, q0 = blockIdx.x * 128;
    extern __shared__ uint32_t S[];
    float* bias = (float*)(S + PW_BIAS);
    int t = threadIdx.x, lane = t & 31, wid = t >> 5;
    int wm = wid & 3, wn = wid >> 2;
    int gp = lane >> 2, tg = lane & 3;
    uint32_t sbase = smem_u32(S);
    if (t < 128) bias[t] = g_beff[g][b][t];
    float acc[2][8][4];
    #pragma unroll
    for (int mt = 0; mt < 2; mt++)
        #pragma unroll
        for (int nt = 0; nt < 8; nt++)
            #pragma unroll
            for (int k = 0; k < 4; k++) acc[mt][nt][k] = 0.f;

    {   // prologue: chunk0
        int e = g_sel[g][b][0];
        const uint4* usrc = (const uint4*)g_ub + ((size_t)(e * BB + b) * UROWS + q0) * 16;
        for (int i = t; i < 512; i += 256) {
            int r = i >> 2, q = i & 3;
            cpa16(sbase + (PW_US0 + r * 20 + q * 4) * 4, usrc + (size_t)r * 16 + q);
        }
        const uint4* wsrc = (const uint4*)g_bp + (size_t)((g * BB + b) * 2 + 0) * 2048;
        for (int i = t; i < 512; i += 256) {
            int co = i >> 2, q = i & 3;
            cpa16(sbase + (PW_WS0 + co * 20 + q * 4) * 4, wsrc + co * 16 + q);
        }
        cpa_commit();
    }

    for (int kc = 0; kc < 8; kc++) {
        if (kc < 7) {
            int kn = kc + 1, slot = kn >> 2, c = kn & 3;
            int e = g_sel[g][b][slot];
            uint32_t uoff = (kn & 1) ? PW_US1 : PW_US0;
            uint32_t woff = (kn & 1) ? PW_WS1 : PW_WS0;
            const uint4* usrc = (const uint4*)g_ub + ((size_t)(e * BB + b) * UROWS + q0) * 16 + c * 4;
            for (int i = t; i < 512; i += 256) {
                int r = i >> 2, q = i & 3;
                cpa16(sbase + (uoff + r * 20 + q * 4) * 4, usrc + (size_t)r * 16 + q);
            }
            const uint4* wsrc = (const uint4*)g_bp + (size_t)((g * BB + b) * 2 + slot) * 2048 + c * 4;
            for (int i = t; i < 512; i += 256) {
                int co = i >> 2, q = i & 3;
                cpa16(sbase + (woff + co * 20 + q * 4) * 4, wsrc + co * 16 + q);
            }
            cpa_commit();
            cpa_wait1();
        } else {
            cpa_wait0();
        }
        __syncthreads();
        const uint32_t* us = S + ((kc & 1) ? PW_US1 : PW_US0);
        const uint32_t* ws = S + ((kc & 1) ? PW_WS1 : PW_WS0);
        int rb = wm * 32 + gp;
        #pragma unroll
        for (int ks = 0; ks < 2; ks++) {
            int k0 = ks * 8 + tg;
            uint32_t a[2][4];
            #pragma unroll
            for (int mt = 0; mt < 2; mt++) {
                const uint32_t* xp = us + (rb + mt * 16) * 20;
                a[mt][0] = xp[k0];
                a[mt][1] = xp[160 + k0];
                a[mt][2] = xp[k0 + 4];
                a[mt][3] = xp[160 + k0 + 4];
            }
            #pragma unroll
            for (int nt = 0; nt < 8; nt++) {
                int n = wn * 64 + nt * 8 + gp;
                uint32_t b0 = ws[n * 20 + k0];
                uint32_t b1 = ws[n * 20 + k0 + 4];
                mma16(acc[0][nt], a[0], b0, b1);
                mma16(acc[1][nt], a[1], b0, b1);
            }
        }
        __syncthreads();
    }

    // epilogue: transpose through smem -> coalesced global stores
    float* stg = (float*)S;
    #pragma unroll
    for (int mt = 0; mt < 2; mt++)
        #pragma unroll
        for (int k = 0; k < 4; k++) {
            int r = wm * 32 + mt * 16 + gp + 8 * (k >> 1);
            #pragma unroll
            for (int nt = 0; nt < 8; nt++) {
                int col = wn * 64 + nt * 8 + 2 * tg + (k & 1);
                stg[col * 132 + r] = acc[mt][nt][k];
            }
        }
    __syncthreads();
    for (int i = t; i < 16384; i += 256) {
        int co = i >> 7, p = i & 127;
        int q = q0 + p;
        int h = q / 98 - 1, w = q % 98 - 1;
        if ((unsigned)h < 96u && (unsigned)w < 96u)
            out[(((size_t)g * BB + b) * CC + co) * PIX + h * 96 + w] =
                stg[co * 132 + p] + bias[co];
    }
}

// ---------------- launch ----------------
extern "C" void kernel_launch(void* const* d_in, const int* in_sizes, int n_in,
                              void* d_out, int out_size) {
    const float* x  = (const float*)d_in[0];
    const float* G  = (const float*)d_in[1];
    const float* Wc = (const float*)d_in[2];
    const float* bc = (const float*)d_in[3];
    const float* Wp = (const float*)d_in[4];
    const float* bp = (const float*)d_in[5];
    float* out = (float*)d_out;

    cudaFuncSetAttribute(k_conv_mma, cudaFuncAttributeMaxDynamicSharedMemorySize, CV_SMEMB);
    cudaFuncSetAttribute(k_pw_mma,   cudaFuncAttributeMaxDynamicSharedMemorySize, PW_SMEMB);

    k_gap<<<BB * CC, 256>>>(x);
    k_gate<<<1, 128>>>(G, bp, out);
    k_packx<<<dim3(144, BB), 256>>>(x);
    k_packw<<<576, 256>>>(Wc);
    k_packbp<<<512, 256>>>(Wp);
    k_conv_mma<<<dim3(NT2, BB, EE), 256, CV_SMEMB>>>(bc);
    k_pw_mma<<<dim3(NTT, BB, NG), 256, PW_SMEMB>>>(out);
}